// round 2
// baseline (speedup 1.0000x reference)
#include <cuda_runtime.h>
#include <cstddef>

#define D 128
#define NEL 200000
#define NGRP 50000
#define CNT_TOT (6*NGRP + 6*NEL)

// ---------------- scratch (device globals: no allocation allowed) ----------------
__device__ float g_el_a[(size_t)NEL * D];
__device__ float g_el_b[(size_t)NEL * D];
__device__ float g_gr_a[(size_t)6 * NGRP * D];
__device__ float g_gr_b[(size_t)6 * NGRP * D];
__device__ float g_agg_el[(size_t)NEL * D];
__device__ float g_agg_gr[(size_t)NGRP * D];
__device__ float g_z[(size_t)NGRP * D];
__device__ int   g_cnt[CNT_TOT];
__device__ float g_inv[CNT_TOT];
__device__ float g_wrsum[4 * D * D];
__device__ float g_bsum[4 * D];
__device__ float g_s[D];

// ---------------- small utility kernels ----------------
__global__ void zero_kernel(float4* p, int n4) {
    int i = blockIdx.x * blockDim.x + threadIdx.x;
    if (i < n4) p[i] = make_float4(0.f, 0.f, 0.f, 0.f);
}

__global__ void count_kernel(const int* __restrict__ dst, int E, int* __restrict__ cnt) {
    int i = blockIdx.x * blockDim.x + threadIdx.x;
    if (i < E) atomicAdd(&cnt[dst[i]], 1);
}

__global__ void inv_kernel(const int* __restrict__ cnt, float* __restrict__ inv, int n) {
    int i = blockIdx.x * blockDim.x + threadIdx.x;
    if (i < n) inv[i] = 1.f / fmaxf((float)cnt[i], 1.f);
}

__global__ void wrsum_kernel(const float* __restrict__ Wr, const float* __restrict__ b,
                             float* __restrict__ wrsum, float* __restrict__ bsum) {
    int i = blockIdx.x * blockDim.x + threadIdx.x;
    if (i < 4 * D * D) {
        int l = i >> 14, idx = i & (D * D - 1);
        float s = 0.f;
        #pragma unroll
        for (int r = 6; r < 12; r++) s += Wr[((size_t)(l * 12 + r) << 14) + idx];
        wrsum[i] = s;
    }
    if (i < 4 * D) {
        int l = i >> 7, idx = i & (D - 1);
        float s = 0.f;
        #pragma unroll
        for (int r = 6; r < 12; r++) s += b[(l * 12 + r) * D + idx];
        bsum[i] = s;
    }
}

// One warp per edge: read a 512B source row, scale by 1/cnt[dst], atomically add to dst row.
__global__ void scatter_kernel(const float* __restrict__ src_feat, const int* __restrict__ esrc,
                               const int* __restrict__ edst, const float* __restrict__ inv,
                               float* __restrict__ agg, int E) {
    int wid = (blockIdx.x * blockDim.x + threadIdx.x) >> 5;
    int lane = threadIdx.x & 31;
    if (wid >= E) return;
    int s = esrc[wid], d = edst[wid];
    float w = inv[d];
    float4 v = *(const float4*)(src_feat + (size_t)s * D + lane * 4);
    float* ap = agg + (size_t)d * D + lane * 4;
    atomicAdd(ap + 0, v.x * w);
    atomicAdd(ap + 1, v.y * w);
    atomicAdd(ap + 2, v.z * w);
    atomicAdd(ap + 3, v.w * w);
}

// ---------------- fused GEMM: out = post( [A@W1 | +A] + [X@W2] + bias ) (+res after relu) ----------------
// MODE bit0: A@W1, bit1: X@W2, bit2: A added elementwise (pre-aggregated term)
template <int MODE>
__global__ void gemm_kernel(const float* __restrict__ A, const float* __restrict__ W1,
                            const float* __restrict__ X, const float* __restrict__ W2,
                            const float* __restrict__ bias, const float* __restrict__ res,
                            float* __restrict__ out, int n, int do_relu) {
    constexpr bool HASW1  = (MODE & 1) != 0;
    constexpr bool HASW2  = (MODE & 2) != 0;
    constexpr bool ADIRECT = (MODE & 4) != 0;
    constexpr bool NEEDA  = HASW1 || ADIRECT;

    extern __shared__ float sm[];
    float* sW1 = sm;                 // 16384
    float* sW2 = sm + 16384;         // 16384
    float* sA  = sm + 32768;         // 32*128
    float* sX  = sA + 4096;          // 32*128

    int t = threadIdx.x;             // 256 threads
    if (HASW1) {
        #pragma unroll
        for (int j = 0; j < 16; j++) {
            int i4 = (t + j * 256) * 4;
            *(float4*)&sW1[i4] = *(const float4*)&W1[i4];
        }
    }
    if (HASW2) {
        #pragma unroll
        for (int j = 0; j < 16; j++) {
            int i4 = (t + j * 256) * 4;
            *(float4*)&sW2[i4] = *(const float4*)&W2[i4];
        }
    }

    int c2 = (t & 63) * 2;           // column pair
    int g  = t >> 6;                 // row group 0..3 (8 rows each)
    int ntiles = (n + 31) >> 5;

    for (int tile = blockIdx.x; tile < ntiles; tile += gridDim.x) {
        int row0 = tile << 5;
        __syncthreads();             // protect previous tile's smem reads
        #pragma unroll
        for (int j = 0; j < 4; j++) {
            int idx4 = t + j * 256;      // float4 index into 32x128 tile
            int off  = idx4 * 4;
            int r    = off >> 7;
            int row  = row0 + r;
            bool ok  = (row < n);
            if (NEEDA) {
                float4 v = ok ? *(const float4*)&A[(size_t)row * D + (off & 127)]
                              : make_float4(0.f, 0.f, 0.f, 0.f);
                *(float4*)&sA[off] = v;
            }
            if (HASW2) {
                float4 v = ok ? *(const float4*)&X[(size_t)row * D + (off & 127)]
                              : make_float4(0.f, 0.f, 0.f, 0.f);
                *(float4*)&sX[off] = v;
            }
        }
        __syncthreads();

        float2 acc[8];
        #pragma unroll
        for (int r = 0; r < 8; r++) acc[r] = make_float2(0.f, 0.f);

        if (HASW1 || HASW2) {
            #pragma unroll 8
            for (int k = 0; k < D; k++) {
                float2 w1, w2;
                if (HASW1) w1 = *(float2*)&sW1[k * D + c2];
                if (HASW2) w2 = *(float2*)&sW2[k * D + c2];
                #pragma unroll
                for (int r = 0; r < 8; r++) {
                    int rr = g * 8 + r;
                    if (HASW1) {
                        float a = sA[rr * D + k];
                        acc[r].x += a * w1.x; acc[r].y += a * w1.y;
                    }
                    if (HASW2) {
                        float x = sX[rr * D + k];
                        acc[r].x += x * w2.x; acc[r].y += x * w2.y;
                    }
                }
            }
        }

        #pragma unroll
        for (int r = 0; r < 8; r++) {
            int rr = g * 8 + r;
            int row = row0 + rr;
            if (row < n) {
                float2 v = acc[r];
                if (ADIRECT) { v.x += sA[rr * D + c2]; v.y += sA[rr * D + c2 + 1]; }
                if (bias)    { v.x += bias[c2];        v.y += bias[c2 + 1]; }
                if (do_relu) { v.x = fmaxf(v.x, 0.f);  v.y = fmaxf(v.y, 0.f); }
                if (res) {
                    float2 rv = *(const float2*)&res[(size_t)row * D + c2];
                    v.x += rv.x; v.y += rv.y;
                }
                *(float2*)&out[(size_t)row * D + c2] = v;
            }
        }
    }
}

__global__ void colmean_kernel(const float* __restrict__ x, int n, float scale,
                               float* __restrict__ out) {
    int j = threadIdx.x;  // 128
    float s = 0.f;
    for (int r = blockIdx.x; r < n; r += gridDim.x) s += x[(size_t)r * D + j];
    atomicAdd(&out[j], s * scale);
}

__global__ void final_kernel(const float* __restrict__ s_in,
                             const float* __restrict__ lin2_w, const float* __restrict__ lin2_b,
                             const float* __restrict__ lin_w, const float* __restrict__ lin_b,
                             float* __restrict__ out) {
    __shared__ float ss[D], sv[D];
    int j = threadIdx.x;
    ss[j] = s_in[j];
    __syncthreads();
    float v = lin2_b[j];
    for (int k = 0; k < D; k++) v += ss[k] * lin2_w[k * D + j];
    sv[j] = v;
    __syncthreads();
    float o = lin_b[j];
    for (int k = 0; k < D; k++) o += sv[k] * lin_w[k * D + j];
    out[j] = o;
}

// ---------------- host orchestration ----------------
static inline int invoff(int r) { return r < 6 ? r * NGRP : 6 * NGRP + (r - 6) * NEL; }

extern "C" void kernel_launch(void* const* d_in, const int* in_sizes, int n_in,
                              void* d_out, int out_size) {
    const float* x_el = (const float*)d_in[0];
    const float* x_gr0[6];
    for (int t = 0; t < 6; t++) x_gr0[t] = (const float*)d_in[1 + t];
    const int* eptr[12];
    for (int r = 0; r < 12; r++) eptr[r] = (const int*)d_in[7 + r];
    const float* Wl     = (const float*)d_in[19];
    const float* Wr     = (const float*)d_in[20];
    const float* bb     = (const float*)d_in[21];
    const float* lin2_w = (const float*)d_in[22];
    const float* lin2_b = (const float*)d_in[23];
    const float* lin_w  = (const float*)d_in[24];
    const float* lin_b  = (const float*)d_in[25];
    float* out = (float*)d_out;
    int E = in_sizes[7] / 2;

    float *el_a, *el_b, *gr_a, *gr_b, *agg_el, *agg_gr, *z, *inv, *wrsum, *bsum, *svec;
    int* cnt;
    cudaGetSymbolAddress((void**)&el_a,   g_el_a);
    cudaGetSymbolAddress((void**)&el_b,   g_el_b);
    cudaGetSymbolAddress((void**)&gr_a,   g_gr_a);
    cudaGetSymbolAddress((void**)&gr_b,   g_gr_b);
    cudaGetSymbolAddress((void**)&agg_el, g_agg_el);
    cudaGetSymbolAddress((void**)&agg_gr, g_agg_gr);
    cudaGetSymbolAddress((void**)&z,      g_z);
    cudaGetSymbolAddress((void**)&cnt,    g_cnt);
    cudaGetSymbolAddress((void**)&inv,    g_inv);
    cudaGetSymbolAddress((void**)&wrsum,  g_wrsum);
    cudaGetSymbolAddress((void**)&bsum,   g_bsum);
    cudaGetSymbolAddress((void**)&svec,   g_s);

    const size_t smem = 40960 * sizeof(float);  // 160 KB
    cudaFuncSetAttribute(gemm_kernel<1>, cudaFuncAttributeMaxDynamicSharedMemorySize, (int)smem);
    cudaFuncSetAttribute(gemm_kernel<3>, cudaFuncAttributeMaxDynamicSharedMemorySize, (int)smem);
    cudaFuncSetAttribute(gemm_kernel<6>, cudaFuncAttributeMaxDynamicSharedMemorySize, (int)smem);

    auto gemm = [&](int mode, const float* A, const float* W1, const float* X, const float* W2,
                    const float* bias, const float* res, float* o, int n, int relu) {
        int ntiles = (n + 31) / 32;
        int grid = ntiles < 148 ? ntiles : 148;
        switch (mode) {
            case 1: gemm_kernel<1><<<grid, 256, smem>>>(A, W1, X, W2, bias, res, o, n, relu); break;
            case 3: gemm_kernel<3><<<grid, 256, smem>>>(A, W1, X, W2, bias, res, o, n, relu); break;
            case 6: gemm_kernel<6><<<grid, 256, smem>>>(A, W1, X, W2, bias, res, o, n, relu); break;
        }
    };
    auto zero = [&](void* p, size_t nfloats) {
        int n4 = (int)(nfloats / 4);
        zero_kernel<<<(n4 + 255) / 256, 256>>>((float4*)p, n4);
    };

    // --- per-relation edge counts -> 1/max(cnt,1) (edges fixed; recomputed each replay) ---
    zero(cnt, CNT_TOT);
    for (int r = 0; r < 12; r++)
        count_kernel<<<(E + 255) / 256, 256>>>(eptr[r] + E, E, cnt + invoff(r));
    inv_kernel<<<(CNT_TOT + 255) / 256, 256>>>(cnt, inv, CNT_TOT);

    // --- summed Wr / b for element dst (relations 6..11 collapse) ---
    wrsum_kernel<<<(4 * D * D + 255) / 256, 256>>>(Wr, bb, wrsum, bsum);

    // --- 4 layers; residual add after layers 1 and 3 (residual == layer input) ---
    for (int l = 0; l < 4; l++) {
        const float* in_el;
        const float* in_gr[6];
        float* out_el;
        float* out_gr;
        if (l == 0) {
            in_el = x_el;
            for (int t = 0; t < 6; t++) in_gr[t] = x_gr0[t];
        } else {
            const float* be = (l == 2) ? el_b : el_a;   // l=1,3 read a; l=2 reads b
            const float* bg = (l == 2) ? gr_b : gr_a;
            in_el = be;
            for (int t = 0; t < 6; t++) in_gr[t] = bg + (size_t)t * NGRP * D;
        }
        out_el = (l % 2 == 0) ? el_a : el_b;
        out_gr = (l % 2 == 0) ? gr_a : gr_b;
        bool use_res = (l == 1 || l == 3);

        // group destinations: aggregate element feats, then fused 2-GEMM + relu (+res)
        for (int t = 0; t < 6; t++) {
            int r = t;
            zero(agg_gr, (size_t)NGRP * D);
            scatter_kernel<<<(E * 32 + 255) / 256, 256>>>(in_el, eptr[r], eptr[r] + E,
                                                          inv + invoff(r), agg_gr, E);
            gemm(3, agg_gr, Wl + ((size_t)(l * 12 + r) << 14),
                 in_gr[t], Wr + ((size_t)(l * 12 + r) << 14),
                 bb + (l * 12 + r) * D,
                 use_res ? in_gr[t] : nullptr,
                 out_gr + (size_t)t * NGRP * D, NGRP, 1);
        }

        // element destination: z = x_t @ Wl (source side!), scatter all 6 into one accumulator
        zero(agg_el, (size_t)NEL * D);
        for (int t = 0; t < 6; t++) {
            int r = 6 + t;
            gemm(1, in_gr[t], Wl + ((size_t)(l * 12 + r) << 14),
                 nullptr, nullptr, nullptr, nullptr, z, NGRP, 0);
            scatter_kernel<<<(E * 32 + 255) / 256, 256>>>(z, eptr[r], eptr[r] + E,
                                                          inv + invoff(r), agg_el, E);
        }
        gemm(6, agg_el, nullptr, in_el, wrsum + (size_t)l * D * D,
             bsum + l * D, use_res ? in_el : nullptr, out_el, NEL, 1);
    }

    // --- outputs: x2 for the 6 group types (Dx lives in *_b after layer 3) ---
    for (int t = 0; t < 6; t++)
        gemm(1, gr_b + (size_t)t * NGRP * D, lin2_w, nullptr, nullptr,
             lin2_b, nullptr, out + 128 + (size_t)t * NGRP * D, NGRP, 0);

    // --- xout via linear pooling shortcut ---
    zero(svec, D);
    colmean_kernel<<<512, 128>>>(el_b, NEL, 1.f / (7.f * NEL), svec);
    for (int t = 0; t < 6; t++)
        colmean_kernel<<<512, 128>>>(gr_b + (size_t)t * NGRP * D, NGRP, 1.f / (7.f * NGRP), svec);
    final_kernel<<<1, 128>>>(svec, lin2_w, lin2_b, lin_w, lin_b, out);
}

// round 3
// speedup vs baseline: 1.9215x; 1.9215x over previous
#include <cuda_runtime.h>
#include <cstddef>

#define D 128
#define NEL 200000
#define NGRP 50000
#define EDG 800000
#define CNT_TOT (6*NGRP + 6*NEL)

typedef unsigned long long ull;

// ---------------- scratch (device globals: no allocation allowed) ----------------
__device__ float g_el_a[(size_t)NEL * D];
__device__ float g_el_b[(size_t)NEL * D];
__device__ float g_gr_a[(size_t)6 * NGRP * D];
__device__ float g_gr_b[(size_t)6 * NGRP * D];
__device__ float g_agg_el[(size_t)NEL * D];
__device__ float g_agg_gr[(size_t)NGRP * D];
__device__ float g_z[(size_t)6 * NGRP * D];
__device__ int   g_cnt[CNT_TOT];
__device__ int   g_rowptr[CNT_TOT + 1];
__device__ int   g_cursor[CNT_TOT];
__device__ int   g_eidx[(size_t)12 * EDG];
__device__ int   g_bsum[2048];
__device__ float g_wrsum[4 * D * D];
__device__ float g_bsumv[4 * D];
__device__ float g_s[D];

// ---------------- f32x2 packed math helpers ----------------
__device__ __forceinline__ ull pk2(float a) {
    unsigned int u = __float_as_uint(a);
    ull r;
    asm("mov.b64 %0, {%1, %1};" : "=l"(r) : "r"(u));
    return r;
}
__device__ __forceinline__ ull fma2(ull a, ull b, ull c) {
    ull d;
    asm("fma.rn.f32x2 %0, %1, %2, %3;" : "=l"(d) : "l"(a), "l"(b), "l"(c));
    return d;
}
__device__ __forceinline__ float2 up2(ull v) {
    unsigned int lo, hi;
    asm("mov.b64 {%0, %1}, %2;" : "=r"(lo), "=r"(hi) : "l"(v));
    return make_float2(__uint_as_float(lo), __uint_as_float(hi));
}

// ---------------- small utility kernels ----------------
__global__ void zero_kernel(float4* p, int n4) {
    int i = blockIdx.x * blockDim.x + threadIdx.x;
    if (i < n4) p[i] = make_float4(0.f, 0.f, 0.f, 0.f);
}

__global__ void count_kernel(const int* __restrict__ dst, int E, int* __restrict__ cnt) {
    int i = blockIdx.x * blockDim.x + threadIdx.x;
    if (i < E) atomicAdd(&cnt[dst[i]], 1);
}

// exclusive scan pass 1: per-block scan + block sums
__global__ void scan1_kernel(const int* __restrict__ cnt, int* __restrict__ rowptr,
                             int* __restrict__ bsum, int n) {
    __shared__ int ws[32];
    int i = blockIdx.x * 1024 + threadIdx.x;
    int lane = threadIdx.x & 31, wid = threadIdx.x >> 5;
    int v = (i < n) ? cnt[i] : 0;
    int x = v;
    #pragma unroll
    for (int o = 1; o < 32; o <<= 1) {
        int y = __shfl_up_sync(0xffffffffu, x, o);
        if (lane >= o) x += y;
    }
    if (lane == 31) ws[wid] = x;
    __syncthreads();
    if (wid == 0) {
        int y = ws[lane];
        #pragma unroll
        for (int o = 1; o < 32; o <<= 1) {
            int z2 = __shfl_up_sync(0xffffffffu, y, o);
            if (lane >= o) y += z2;
        }
        ws[lane] = y;
    }
    __syncthreads();
    int base = wid ? ws[wid - 1] : 0;
    if (i < n) rowptr[i] = base + x - v;
    if (threadIdx.x == 0) bsum[blockIdx.x] = ws[31];
}

// exclusive scan pass 2: single-block scan of block sums (with carry)
__global__ void scan2_kernel(int* __restrict__ bsum, int nb) {
    __shared__ int ws[32];
    __shared__ int carry;
    int lane = threadIdx.x & 31, wid = threadIdx.x >> 5;
    if (threadIdx.x == 0) carry = 0;
    __syncthreads();
    for (int s = 0; s < nb; s += 1024) {
        int i = s + threadIdx.x;
        int v = (i < nb) ? bsum[i] : 0;
        int x = v;
        #pragma unroll
        for (int o = 1; o < 32; o <<= 1) {
            int y = __shfl_up_sync(0xffffffffu, x, o);
            if (lane >= o) x += y;
        }
        if (lane == 31) ws[wid] = x;
        __syncthreads();
        if (wid == 0) {
            int y = ws[lane];
            #pragma unroll
            for (int o = 1; o < 32; o <<= 1) {
                int z2 = __shfl_up_sync(0xffffffffu, y, o);
                if (lane >= o) y += z2;
            }
            ws[lane] = y;
        }
        __syncthreads();
        int base = carry + (wid ? ws[wid - 1] : 0);
        int tot = ws[31];
        if (i < nb) bsum[i] = base + x - v;
        __syncthreads();
        if (threadIdx.x == 0) carry += tot;
        __syncthreads();
    }
}

// pass 3: add block offsets, set sentinel, init cursor
__global__ void scan3_kernel(int* __restrict__ rowptr, const int* __restrict__ bsum,
                             int* __restrict__ cursor, int n, int total) {
    int i = blockIdx.x * blockDim.x + threadIdx.x;
    if (i < n) {
        int v = rowptr[i] + bsum[i >> 10];
        rowptr[i] = v;
        cursor[i] = v;
    }
    if (i == 0) rowptr[n] = total;
}

__global__ void fill_kernel(const int* __restrict__ src, const int* __restrict__ dst, int E,
                            int* __restrict__ cursor_seg, int* __restrict__ eidx) {
    int i = blockIdx.x * blockDim.x + threadIdx.x;
    if (i < E) {
        int p = atomicAdd(&cursor_seg[dst[i]], 1);
        eidx[p] = src[i];
    }
}

__global__ void wrsum_kernel(const float* __restrict__ Wr, const float* __restrict__ b,
                             float* __restrict__ wrsum, float* __restrict__ bsum) {
    int i = blockIdx.x * blockDim.x + threadIdx.x;
    if (i < 4 * D * D) {
        int l = i >> 14, idx = i & (D * D - 1);
        float s = 0.f;
        #pragma unroll
        for (int r = 6; r < 12; r++) s += Wr[((size_t)(l * 12 + r) << 14) + idx];
        wrsum[i] = s;
    }
    if (i < 4 * D) {
        int l = i >> 7, idx = i & (D - 1);
        float s = 0.f;
        #pragma unroll
        for (int r = 6; r < 12; r++) s += b[(l * 12 + r) * D + idx];
        bsum[i] = s;
    }
}

// ---------------- gather aggregation (CSR, no atomics) ----------------
// One warp per dst node; lane owns 4 floats. out[d] = mean over edges of src_feat[src].
__global__ void gather_kernel(const float* __restrict__ src_feat, const int* __restrict__ rowptr_seg,
                              const int* __restrict__ eidx, float* __restrict__ out, int n) {
    int w = (blockIdx.x * blockDim.x + threadIdx.x) >> 5;
    int lane = threadIdx.x & 31;
    if (w >= n) return;
    int beg = rowptr_seg[w], end = rowptr_seg[w + 1];
    float4 acc = make_float4(0.f, 0.f, 0.f, 0.f);
    int c = lane * 4;
    for (int e = beg; e < end; e++) {
        int s = __ldg(&eidx[e]);
        float4 v = *(const float4*)&src_feat[(size_t)s * D + c];
        acc.x += v.x; acc.y += v.y; acc.z += v.z; acc.w += v.w;
    }
    float inv = 1.f / fmaxf((float)(end - beg), 1.f);
    acc.x *= inv; acc.y *= inv; acc.z *= inv; acc.w *= inv;
    *(float4*)&out[(size_t)w * D + c] = acc;
}

// Merged element-dst gather over the 6 reverse relations (z holds 6 stacked tables).
__global__ void gather_el_kernel(const float* __restrict__ z, const int* __restrict__ rowptr,
                                 const int* __restrict__ eidx, float* __restrict__ out) {
    int w = (blockIdx.x * blockDim.x + threadIdx.x) >> 5;
    int lane = threadIdx.x & 31;
    if (w >= NEL) return;
    int c = lane * 4;
    float4 acc = make_float4(0.f, 0.f, 0.f, 0.f);
    #pragma unroll
    for (int t = 0; t < 6; t++) {
        int segbase = 6 * NGRP + t * NEL;
        int beg = rowptr[segbase + w], end = rowptr[segbase + w + 1];
        float4 a2 = make_float4(0.f, 0.f, 0.f, 0.f);
        const float* zt = z + (size_t)t * NGRP * D;
        for (int e = beg; e < end; e++) {
            int s = __ldg(&eidx[e]);
            float4 v = *(const float4*)&zt[(size_t)s * D + c];
            a2.x += v.x; a2.y += v.y; a2.z += v.z; a2.w += v.w;
        }
        float inv = 1.f / fmaxf((float)(end - beg), 1.f);
        acc.x += a2.x * inv; acc.y += a2.y * inv; acc.z += a2.z * inv; acc.w += a2.w * inv;
    }
    *(float4*)&out[(size_t)w * D + c] = acc;
}

// ---------------- fused GEMM with packed f32x2 FMA ----------------
// MODE bit0: A@W1, bit1: X@W2, bit2: A added elementwise.
// out = post( [A@W1 | +A] + [X@W2] + bias ) (+res after relu)
template <int MODE>
__global__ void gemm_kernel(const float* __restrict__ A, const float* __restrict__ W1,
                            const float* __restrict__ X, const float* __restrict__ W2,
                            const float* __restrict__ bias, const float* __restrict__ res,
                            float* __restrict__ out, int n, int do_relu) {
    constexpr bool HASW1  = (MODE & 1) != 0;
    constexpr bool HASW2  = (MODE & 2) != 0;
    constexpr bool ADIRECT = (MODE & 4) != 0;
    constexpr bool NEEDA  = HASW1 || ADIRECT;

    extern __shared__ float sm[];
    float* p = sm;
    float* sW1 = nullptr; float* sW2 = nullptr; float* sA = nullptr; float* sX = nullptr;
    if (HASW1) { sW1 = p; p += 16384; }
    if (HASW2) { sW2 = p; p += 16384; }
    if (NEEDA) { sA = p; p += 64 * D; }
    if (HASW2) { sX = p; p += 64 * D; }

    int t = threadIdx.x;  // 256 threads
    if (HASW1) {
        #pragma unroll
        for (int j = 0; j < 16; j++) {
            int i4 = (t + j * 256) * 4;
            *(float4*)&sW1[i4] = *(const float4*)&W1[i4];
        }
    }
    if (HASW2) {
        #pragma unroll
        for (int j = 0; j < 16; j++) {
            int i4 = (t + j * 256) * 4;
            *(float4*)&sW2[i4] = *(const float4*)&W2[i4];
        }
    }

    int cp = (t & 15) * 8;   // column start (8 cols = 4 pairs)
    int rg = (t >> 4) * 4;   // row start within 64-row tile (4 rows)
    int ntiles = (n + 63) >> 6;

    for (int tile = blockIdx.x; tile < ntiles; tile += gridDim.x) {
        int row0 = tile << 6;
        __syncthreads();
        #pragma unroll
        for (int j = 0; j < 8; j++) {
            int i4 = t + j * 256;
            int off = i4 * 4;
            int r = off >> 7;
            int row = row0 + r;
            int cc = off & 127;
            bool ok = (row < n);
            if (NEEDA) {
                float4 v = ok ? *(const float4*)&A[(size_t)row * D + cc]
                              : make_float4(0.f, 0.f, 0.f, 0.f);
                *(float4*)&sA[off] = v;
            }
            if (HASW2) {
                float4 v = ok ? *(const float4*)&X[(size_t)row * D + cc]
                              : make_float4(0.f, 0.f, 0.f, 0.f);
                *(float4*)&sX[off] = v;
            }
        }
        __syncthreads();

        ull acc[4][4];
        #pragma unroll
        for (int r = 0; r < 4; r++)
            #pragma unroll
            for (int j = 0; j < 4; j++) acc[r][j] = 0ull;

        if (HASW1 || HASW2) {
            #pragma unroll 4
            for (int k = 0; k < D; k++) {
                ulonglong2 w1a, w1b, w2a, w2b;
                if (HASW1) {
                    w1a = *(ulonglong2*)&sW1[k * D + cp];
                    w1b = *(ulonglong2*)&sW1[k * D + cp + 4];
                }
                if (HASW2) {
                    w2a = *(ulonglong2*)&sW2[k * D + cp];
                    w2b = *(ulonglong2*)&sW2[k * D + cp + 4];
                }
                #pragma unroll
                for (int r = 0; r < 4; r++) {
                    if (HASW1) {
                        ull aa = pk2(sA[(rg + r) * D + k]);
                        acc[r][0] = fma2(aa, w1a.x, acc[r][0]);
                        acc[r][1] = fma2(aa, w1a.y, acc[r][1]);
                        acc[r][2] = fma2(aa, w1b.x, acc[r][2]);
                        acc[r][3] = fma2(aa, w1b.y, acc[r][3]);
                    }
                    if (HASW2) {
                        ull xx = pk2(sX[(rg + r) * D + k]);
                        acc[r][0] = fma2(xx, w2a.x, acc[r][0]);
                        acc[r][1] = fma2(xx, w2a.y, acc[r][1]);
                        acc[r][2] = fma2(xx, w2b.x, acc[r][2]);
                        acc[r][3] = fma2(xx, w2b.y, acc[r][3]);
                    }
                }
            }
        }

        #pragma unroll
        for (int r = 0; r < 4; r++) {
            int rr = rg + r;
            int row = row0 + rr;
            if (row < n) {
                float2 v[4];
                #pragma unroll
                for (int j = 0; j < 4; j++) v[j] = up2(acc[r][j]);
                if (ADIRECT) {
                    #pragma unroll
                    for (int j = 0; j < 4; j++) {
                        v[j].x += sA[rr * D + cp + 2 * j];
                        v[j].y += sA[rr * D + cp + 2 * j + 1];
                    }
                }
                if (bias) {
                    float4 b0 = *(const float4*)&bias[cp];
                    float4 b1 = *(const float4*)&bias[cp + 4];
                    v[0].x += b0.x; v[0].y += b0.y; v[1].x += b0.z; v[1].y += b0.w;
                    v[2].x += b1.x; v[2].y += b1.y; v[3].x += b1.z; v[3].y += b1.w;
                }
                if (do_relu) {
                    #pragma unroll
                    for (int j = 0; j < 4; j++) {
                        v[j].x = fmaxf(v[j].x, 0.f);
                        v[j].y = fmaxf(v[j].y, 0.f);
                    }
                }
                if (res) {
                    float4 r0 = *(const float4*)&res[(size_t)row * D + cp];
                    float4 r1 = *(const float4*)&res[(size_t)row * D + cp + 4];
                    v[0].x += r0.x; v[0].y += r0.y; v[1].x += r0.z; v[1].y += r0.w;
                    v[2].x += r1.x; v[2].y += r1.y; v[3].x += r1.z; v[3].y += r1.w;
                }
                float4 o0 = make_float4(v[0].x, v[0].y, v[1].x, v[1].y);
                float4 o1 = make_float4(v[2].x, v[2].y, v[3].x, v[3].y);
                *(float4*)&out[(size_t)row * D + cp] = o0;
                *(float4*)&out[(size_t)row * D + cp + 4] = o1;
            }
        }
    }
}

__global__ void colmean_kernel(const float* __restrict__ x, int n, float scale,
                               float* __restrict__ out) {
    int j = threadIdx.x;  // 128
    float s = 0.f;
    for (int r = blockIdx.x; r < n; r += gridDim.x) s += x[(size_t)r * D + j];
    atomicAdd(&out[j], s * scale);
}

__global__ void final_kernel(const float* __restrict__ s_in,
                             const float* __restrict__ lin2_w, const float* __restrict__ lin2_b,
                             const float* __restrict__ lin_w, const float* __restrict__ lin_b,
                             float* __restrict__ out) {
    __shared__ float ss[D], sv[D];
    int j = threadIdx.x;
    ss[j] = s_in[j];
    __syncthreads();
    float v = lin2_b[j];
    for (int k = 0; k < D; k++) v += ss[k] * lin2_w[k * D + j];
    sv[j] = v;
    __syncthreads();
    float o = lin_b[j];
    for (int k = 0; k < D; k++) o += sv[k] * lin_w[k * D + j];
    out[j] = o;
}

// ---------------- host orchestration ----------------
static inline int segoff(int r) { return r < 6 ? r * NGRP : 6 * NGRP + (r - 6) * NEL; }

extern "C" void kernel_launch(void* const* d_in, const int* in_sizes, int n_in,
                              void* d_out, int out_size) {
    const float* x_el = (const float*)d_in[0];
    const float* x_gr0[6];
    for (int t = 0; t < 6; t++) x_gr0[t] = (const float*)d_in[1 + t];
    const int* eptr[12];
    for (int r = 0; r < 12; r++) eptr[r] = (const int*)d_in[7 + r];
    const float* Wl     = (const float*)d_in[19];
    const float* Wr     = (const float*)d_in[20];
    const float* bb     = (const float*)d_in[21];
    const float* lin2_w = (const float*)d_in[22];
    const float* lin2_b = (const float*)d_in[23];
    const float* lin_w  = (const float*)d_in[24];
    const float* lin_b  = (const float*)d_in[25];
    float* out = (float*)d_out;
    int E = in_sizes[7] / 2;

    float *el_a, *el_b, *gr_a, *gr_b, *agg_el, *agg_gr, *z, *wrsum, *bsumv, *svec;
    int *cnt, *rowptr, *cursor, *eidx, *bsum;
    cudaGetSymbolAddress((void**)&el_a,   g_el_a);
    cudaGetSymbolAddress((void**)&el_b,   g_el_b);
    cudaGetSymbolAddress((void**)&gr_a,   g_gr_a);
    cudaGetSymbolAddress((void**)&gr_b,   g_gr_b);
    cudaGetSymbolAddress((void**)&agg_el, g_agg_el);
    cudaGetSymbolAddress((void**)&agg_gr, g_agg_gr);
    cudaGetSymbolAddress((void**)&z,      g_z);
    cudaGetSymbolAddress((void**)&cnt,    g_cnt);
    cudaGetSymbolAddress((void**)&rowptr, g_rowptr);
    cudaGetSymbolAddress((void**)&cursor, g_cursor);
    cudaGetSymbolAddress((void**)&eidx,   g_eidx);
    cudaGetSymbolAddress((void**)&bsum,   g_bsum);
    cudaGetSymbolAddress((void**)&wrsum,  g_wrsum);
    cudaGetSymbolAddress((void**)&bsumv,  g_bsumv);
    cudaGetSymbolAddress((void**)&svec,   g_s);

    const int SMEM1 = (16384 + 8192) * 4;               // 96 KB
    const int SMEM3 = (2 * 16384 + 2 * 8192) * 4;       // 192 KB
    const int SMEM6 = (16384 + 2 * 8192) * 4;           // 128 KB
    cudaFuncSetAttribute(gemm_kernel<1>, cudaFuncAttributeMaxDynamicSharedMemorySize, SMEM1);
    cudaFuncSetAttribute(gemm_kernel<3>, cudaFuncAttributeMaxDynamicSharedMemorySize, SMEM3);
    cudaFuncSetAttribute(gemm_kernel<6>, cudaFuncAttributeMaxDynamicSharedMemorySize, SMEM6);

    auto gemm = [&](int mode, const float* A, const float* W1, const float* X, const float* W2,
                    const float* bias, const float* res, float* o, int n, int relu) {
        int ntiles = (n + 63) / 64;
        int maxgrid = (mode == 1) ? 296 : 148;
        int grid = ntiles < maxgrid ? ntiles : maxgrid;
        switch (mode) {
            case 1: gemm_kernel<1><<<grid, 256, SMEM1>>>(A, W1, X, W2, bias, res, o, n, relu); break;
            case 3: gemm_kernel<3><<<grid, 256, SMEM3>>>(A, W1, X, W2, bias, res, o, n, relu); break;
            case 6: gemm_kernel<6><<<grid, 256, SMEM6>>>(A, W1, X, W2, bias, res, o, n, relu); break;
        }
    };

    // --- CSR build (per replay; edges are inputs) ---
    {
        int n4 = CNT_TOT / 4;
        zero_kernel<<<(n4 + 255) / 256, 256>>>((float4*)cnt, n4);
    }
    for (int r = 0; r < 12; r++)
        count_kernel<<<(E + 255) / 256, 256>>>(eptr[r] + E, E, cnt + segoff(r));
    int nb = (CNT_TOT + 1023) / 1024;
    scan1_kernel<<<nb, 1024>>>(cnt, rowptr, bsum, CNT_TOT);
    scan2_kernel<<<1, 1024>>>(bsum, nb);
    scan3_kernel<<<nb, 1024>>>(rowptr, bsum, cursor, CNT_TOT, 12 * E);
    for (int r = 0; r < 12; r++)
        fill_kernel<<<(E + 255) / 256, 256>>>(eptr[r], eptr[r] + E, E, cursor + segoff(r), eidx);

    // --- summed Wr / b for element dst (relations 6..11 collapse) ---
    wrsum_kernel<<<(4 * D * D + 255) / 256, 256>>>(Wr, bb, wrsum, bsumv);

    // --- 4 layers; residual add after layers 1 and 3 ---
    for (int l = 0; l < 4; l++) {
        const float* in_el;
        const float* in_gr[6];
        if (l == 0) {
            in_el = x_el;
            for (int t = 0; t < 6; t++) in_gr[t] = x_gr0[t];
        } else {
            const float* be = (l == 2) ? el_b : el_a;
            const float* bg = (l == 2) ? gr_b : gr_a;
            in_el = be;
            for (int t = 0; t < 6; t++) in_gr[t] = bg + (size_t)t * NGRP * D;
        }
        float* out_el = (l % 2 == 0) ? el_a : el_b;
        float* out_gr = (l % 2 == 0) ? gr_a : gr_b;
        bool use_res = (l == 1 || l == 3);

        // group destinations: gather mean of element feats, fused 2-GEMM + relu (+res)
        for (int t = 0; t < 6; t++) {
            int r = t;
            gather_kernel<<<(NGRP * 32 + 255) / 256, 256>>>(in_el, rowptr + segoff(r),
                                                            eidx, agg_gr, NGRP);
            gemm(3, agg_gr, Wl + ((size_t)(l * 12 + r) << 14),
                 in_gr[t], Wr + ((size_t)(l * 12 + r) << 14),
                 bb + (l * 12 + r) * D,
                 use_res ? in_gr[t] : nullptr,
                 out_gr + (size_t)t * NGRP * D, NGRP, 1);
        }

        // element destination: z_t = x_t @ Wl (source side), then merged gather over 6 rels
        for (int t = 0; t < 6; t++) {
            int r = 6 + t;
            gemm(1, in_gr[t], Wl + ((size_t)(l * 12 + r) << 14),
                 nullptr, nullptr, nullptr, nullptr, z + (size_t)t * NGRP * D, NGRP, 0);
        }
        gather_el_kernel<<<(NEL * 32 + 255) / 256, 256>>>(z, rowptr, eidx, agg_el);
        gemm(6, agg_el, nullptr, in_el, wrsum + (size_t)l * D * D,
             bsumv + l * D, use_res ? in_el : nullptr, out_el, NEL, 1);
    }

    // --- outputs: x2 for the 6 group types ---
    for (int t = 0; t < 6; t++)
        gemm(1, gr_b + (size_t)t * NGRP * D, lin2_w, nullptr, nullptr,
             lin2_b, nullptr, out + 128 + (size_t)t * NGRP * D, NGRP, 0);

    // --- xout via linear pooling shortcut ---
    zero_kernel<<<1, 32>>>((float4*)svec, 32);
    colmean_kernel<<<512, 128>>>(el_b, NEL, 1.f / (7.f * NEL), svec);
    for (int t = 0; t < 6; t++)
        colmean_kernel<<<512, 128>>>(gr_b + (size_t)t * NGRP * D, NGRP, 1.f / (7.f * NGRP), svec);
    final_kernel<<<1, 128>>>(svec, lin2_w, lin2_b, lin_w, lin_b, out);
}